// round 4
// baseline (speedup 1.0000x reference)
#include <cuda_runtime.h>
#include <cstdint>

#define Bn    64
#define Cn    16
#define Hn    48
#define Wn    48
#define COUT  128
#define OHn   44
#define OWn   44
#define Pn    1936
#define Fn    400
#define KC    40            // K-chunk (400 = 10 * 40)
#define NCHUNK 10
#define A_STRIDE 72         // 64 + 8 pad (bank-conflict-free frags)
#define B_STRIDE 136        // 128 + 8 pad
#define STAGE_FLOATS (KC*A_STRIDE + KC*B_STRIDE)   // 2880 + 5440 = 8320
#define SMEM_BYTES   (2*STAGE_FLOATS*4)            // 66560

// ---------------- scratch (device globals: no allocations allowed) ----------
__device__ float g_xT[Cn*Hn*Wn*Bn];                 // normalized, tf32-rounded, [chw][b]
__device__ float g_scratch[(size_t)Pn*Bn*COUT];     // GEMM out [p][b][c]
__device__ float g_inv[Bn];
__device__ float g_sum[COUT];
__device__ float g_sq[COUT];

// ---------------- small PTX helpers -----------------------------------------
__device__ __forceinline__ uint32_t f2tf32(float f) {
    uint32_t u;
    asm("cvt.rna.tf32.f32 %0, %1;" : "=r"(u) : "f"(f));
    return u;
}
__device__ __forceinline__ void cp16(uint32_t smem_dst, const void* gmem_src) {
    asm volatile("cp.async.cg.shared.global [%0], [%1], 16;\n"
                 :: "r"(smem_dst), "l"(gmem_src));
}
__device__ __forceinline__ void mma_tf32(float* c, const uint32_t* a, const uint32_t* b) {
    asm volatile(
        "mma.sync.aligned.m16n8k8.row.col.f32.tf32.tf32.f32 "
        "{%0,%1,%2,%3}, {%4,%5,%6,%7}, {%8,%9}, {%0,%1,%2,%3};\n"
        : "+f"(c[0]), "+f"(c[1]), "+f"(c[2]), "+f"(c[3])
        : "r"(a[0]), "r"(a[1]), "r"(a[2]), "r"(a[3]), "r"(b[0]), "r"(b[1]));
}

// ---------------- K1: per-batch L2 norm + zero BN stats ---------------------
__global__ void k_norm(const float* __restrict__ x) {
    int b = blockIdx.x, tid = threadIdx.x;
    if (tid < 4) {                      // 64 blocks * 4 = 256 entries
        int i = b * 4 + tid;
        if (i < COUT) g_sum[i] = 0.f; else g_sq[i - COUT] = 0.f;
    }
    const float4* xb = (const float4*)(x + b * (Cn*Hn*Wn));
    float s = 0.f;
    #pragma unroll
    for (int j = 0; j < 36; ++j) {      // 36 * 256 = 9216 float4 = 36864 floats
        float4 v = xb[tid + j * 256];
        s += v.x*v.x + v.y*v.y + v.z*v.z + v.w*v.w;
    }
    __shared__ float red[8];
    #pragma unroll
    for (int o = 16; o; o >>= 1) s += __shfl_xor_sync(~0u, s, o);
    if ((tid & 31) == 0) red[tid >> 5] = s;
    __syncthreads();
    if (tid < 32) {
        float t = (tid < 8) ? red[tid] : 0.f;
        #pragma unroll
        for (int o = 4; o; o >>= 1) t += __shfl_xor_sync(~0u, t, o);
        if (tid == 0) g_inv[b] = 1.f / (sqrtf(t) + 1e-7f);
    }
}

// ---------------- K2: normalize + transpose x -> xT[chw][b] (tf32-rounded) --
__global__ void k_xt(const float* __restrict__ x) {
    __shared__ float tile[64][33];
    int chw0 = blockIdx.x * 32;
    int tx = threadIdx.x & 31, ty = threadIdx.x >> 5;
    #pragma unroll
    for (int i = 0; i < 8; ++i) {
        int bb = ty + i * 8;
        float v = x[bb * (Cn*Hn*Wn) + chw0 + tx] * g_inv[bb];
        tile[bb][tx] = __uint_as_float(f2tf32(v));
    }
    __syncthreads();
    #pragma unroll
    for (int i = 0; i < 8; ++i) {
        int idx = threadIdx.x + i * 256;
        int cl = idx >> 6, bb = idx & 63;
        g_xT[(chw0 + cl) * 64 + bb] = tile[bb][cl];
    }
}

// ---------------- K3: per-position GEMM (tf32 mma.sync, cp.async pipeline) --
__device__ __forceinline__ void load_chunk(float* Abuf, float* Bbuf,
                                           const float* kbase,
                                           int k0, int oh, int ow, int tid) {
    // A: 40 rows (f) x 64 (b), gathered from xT (batch-contiguous -> 16B pieces)
    #pragma unroll
    for (int j = 0; j < 3; ++j) {                  // 640 cp.async / 256 thr
        int idx = tid + j * 256;
        if (idx < KC * 16) {
            int kk   = idx >> 4, mseg = idx & 15;
            int f    = k0 + kk;
            int c    = f / 25; int rem = f - c * 25;
            int r    = rem / 5; int s = rem - r * 5;
            const float* src = g_xT + ((c * Hn + oh + r) * Wn + (ow + s)) * 64 + mseg * 4;
            cp16((uint32_t)__cvta_generic_to_shared(&Abuf[kk * A_STRIDE + mseg * 4]), src);
        }
    }
    // B: 40 rows (f) x 128 (cout), pure stream
    #pragma unroll
    for (int j = 0; j < 5; ++j) {                  // 1280 cp.async / 256 thr
        int idx  = tid + j * 256;
        int kk   = idx >> 5, nseg = idx & 31;
        const float* src = kbase + (k0 + kk) * COUT + nseg * 4;
        cp16((uint32_t)__cvta_generic_to_shared(&Bbuf[kk * B_STRIDE + nseg * 4]), src);
    }
    asm volatile("cp.async.commit_group;\n");
}

__global__ void __launch_bounds__(256, 2) k_gemm(const float* __restrict__ kern) {
    extern __shared__ float sm[];
    const int p = blockIdx.x;
    const int oh = p / OWn, ow = p - oh * OWn;
    const int tid = threadIdx.x;
    const int lane = tid & 31, warp = tid >> 5;
    const int g = lane >> 2, tg = lane & 3;
    const int m_off = (warp >> 2) * 32;   // 2 warps over M=64
    const int n_off = (warp & 3) * 32;    // 4 warps over N=128
    const int mhalf = warp >> 2;

    float* Abuf[2] = { sm,                 sm + STAGE_FLOATS };
    float* Bbuf[2] = { sm + KC*A_STRIDE,   sm + STAGE_FLOATS + KC*A_STRIDE };

    const float* kbase = kern + (size_t)p * (Fn * COUT);

    float acc[2][4][4];
    #pragma unroll
    for (int mt = 0; mt < 2; ++mt)
        #pragma unroll
        for (int nt = 0; nt < 4; ++nt)
            #pragma unroll
            for (int q = 0; q < 4; ++q) acc[mt][nt][q] = 0.f;

    load_chunk(Abuf[0], Bbuf[0], kbase, 0, oh, ow, tid);

    for (int ch = 0; ch < NCHUNK; ++ch) {
        if (ch + 1 < NCHUNK) {
            load_chunk(Abuf[(ch+1)&1], Bbuf[(ch+1)&1], kbase, (ch+1)*KC, oh, ow, tid);
            asm volatile("cp.async.wait_group 1;\n");
        } else {
            asm volatile("cp.async.wait_group 0;\n");
        }
        __syncthreads();

        const uint32_t* As = (const uint32_t*)Abuf[ch & 1];  // already tf32
        const float*    Bs = Bbuf[ch & 1];

        #pragma unroll
        for (int ks = 0; ks < KC; ks += 8) {
            uint32_t a[2][4], b[4][2];
            #pragma unroll
            for (int mt = 0; mt < 2; ++mt) {
                int rm = m_off + mt * 16 + g;
                a[mt][0] = As[(ks + tg    ) * A_STRIDE + rm    ];
                a[mt][1] = As[(ks + tg    ) * A_STRIDE + rm + 8];
                a[mt][2] = As[(ks + tg + 4) * A_STRIDE + rm    ];
                a[mt][3] = As[(ks + tg + 4) * A_STRIDE + rm + 8];
            }
            #pragma unroll
            for (int nt = 0; nt < 4; ++nt) {
                int cn = n_off + nt * 8 + g;
                b[nt][0] = f2tf32(Bs[(ks + tg    ) * B_STRIDE + cn]);
                b[nt][1] = f2tf32(Bs[(ks + tg + 4) * B_STRIDE + cn]);
            }
            #pragma unroll
            for (int mt = 0; mt < 2; ++mt)
                #pragma unroll
                for (int nt = 0; nt < 4; ++nt)
                    mma_tf32(acc[mt][nt], a[mt], b[nt]);
        }
        __syncthreads();
    }

    // epilogue 1: scratch[p][b][c] (coalesced float2 stores)
    float* outp = g_scratch + (size_t)p * (Bn * COUT);
    #pragma unroll
    for (int mt = 0; mt < 2; ++mt)
        #pragma unroll
        for (int nt = 0; nt < 4; ++nt) {
            int row = m_off + mt * 16 + g;
            int col = n_off + nt * 8 + 2 * tg;
            *(float2*)(outp + row * COUT + col)       = make_float2(acc[mt][nt][0], acc[mt][nt][1]);
            *(float2*)(outp + (row + 8) * COUT + col) = make_float2(acc[mt][nt][2], acc[mt][nt][3]);
        }

    // epilogue 2: fused BN statistics (per-channel sum / sumsq over M=64 rows)
    float ps[4][2], pq[4][2];
    #pragma unroll
    for (int nt = 0; nt < 4; ++nt)
        #pragma unroll
        for (int j = 0; j < 2; ++j) {
            float v0 = acc[0][nt][j],     v1 = acc[0][nt][j + 2];
            float v2 = acc[1][nt][j],     v3 = acc[1][nt][j + 2];
            ps[nt][j] = v0 + v1 + v2 + v3;
            pq[nt][j] = v0*v0 + v1*v1 + v2*v2 + v3*v3;
        }
    // reduce across g (lane bits 2..4): warp's 32 rows collapse per column
    #pragma unroll
    for (int o = 4; o < 32; o <<= 1)
        #pragma unroll
        for (int nt = 0; nt < 4; ++nt)
            #pragma unroll
            for (int j = 0; j < 2; ++j) {
                ps[nt][j] += __shfl_xor_sync(~0u, ps[nt][j], o);
                pq[nt][j] += __shfl_xor_sync(~0u, pq[nt][j], o);
            }
    // smem combine: sm[0..255] = S[mhalf][c], sm[256..511] = Q[mhalf][c]
    if (g == 0) {
        #pragma unroll
        for (int nt = 0; nt < 4; ++nt)
            #pragma unroll
            for (int j = 0; j < 2; ++j) {
                int col = n_off + nt * 8 + 2 * tg + j;
                sm[mhalf * COUT + col]            = ps[nt][j];
                sm[2 * COUT + mhalf * COUT + col] = pq[nt][j];
            }
    }
    __syncthreads();
    if (tid < COUT) {
        atomicAdd(&g_sum[tid], sm[tid] + sm[COUT + tid]);
    } else {
        int c = tid - COUT;
        atomicAdd(&g_sq[c], sm[2 * COUT + c] + sm[3 * COUT + c]);
    }
}

// ---------------- K4: BN + ReLU + transpose -> (B, COUT, OH, OW) ------------
__global__ void k_out(const float* __restrict__ gamma, const float* __restrict__ beta,
                      float* __restrict__ out) {
    __shared__ float tile[32][33];
    __shared__ float s_scale[32], s_shift[32];
    const float inv_cnt = 1.f / (float)(Bn * Pn);
    int bx = blockIdx.x, cy = blockIdx.y, b = blockIdx.z;
    int tx = threadIdx.x, ty = threadIdx.y;
    int tid = ty * 32 + tx;
    if (tid < 32) {
        int c = cy * 32 + tid;
        float mean = g_sum[c] * inv_cnt;
        float var  = g_sq[c] * inv_cnt - mean * mean;
        float istd = rsqrtf(var + 1e-5f);
        float sc = gamma[c] * istd;
        s_scale[tid] = sc;
        s_shift[tid] = beta[c] - mean * sc;
    }
    int p0 = bx * 32;
    #pragma unroll
    for (int i = 0; i < 4; ++i) {
        int pl = ty + i * 8;
        int pp = p0 + pl;
        float v = 0.f;
        if (pp < Pn) v = g_scratch[(size_t)(pp * Bn + b) * COUT + cy * 32 + tx];
        tile[pl][tx] = v;
    }
    __syncthreads();
    #pragma unroll
    for (int i = 0; i < 4; ++i) {
        int cl = ty + i * 8;
        int pp = p0 + tx;
        if (pp < Pn) {
            float v = tile[tx][cl];
            v = fmaxf(v * s_scale[cl] + s_shift[cl], 0.f);
            out[((size_t)(b * COUT + cy * 32 + cl)) * Pn + pp] = v;
        }
    }
}

// ---------------- launch -----------------------------------------------------
extern "C" void kernel_launch(void* const* d_in, const int* in_sizes, int n_in,
                              void* d_out, int out_size) {
    const float* x     = (const float*)d_in[0];
    const float* kern  = (const float*)d_in[1];
    const float* gamma = (const float*)d_in[2];
    const float* beta  = (const float*)d_in[3];
    float* out = (float*)d_out;
    (void)in_sizes; (void)n_in; (void)out_size;

    k_norm<<<Bn, 256>>>(x);
    k_xt<<<(Cn*Hn*Wn)/32, 256>>>(x);
    cudaFuncSetAttribute(k_gemm, cudaFuncAttributeMaxDynamicSharedMemorySize, SMEM_BYTES);
    k_gemm<<<Pn, 256, SMEM_BYTES>>>(kern);
    dim3 g5((Pn + 31) / 32, COUT / 32, Bn), b5(32, 8);
    k_out<<<g5, b5>>>(gamma, beta, out);
}

// round 6
// speedup vs baseline: 1.0779x; 1.0779x over previous
#include <cuda_runtime.h>
#include <cuda_fp16.h>
#include <cstdint>

#define Bn    64
#define Cn    16
#define Hn    48
#define Wn    48
#define COUT  128
#define OHn   44
#define OWn   44
#define Pn    1936
#define Fn    400
#define KC    16            // K-chunk (400 = 25 * 16)
#define NCHUNK 25
#define STAGES 6
#define PREF   4            // prefetch depth (loads in flight)
#define A_STRIDE 72         // 64 + 8 pad
#define B_STRIDE 136        // 128 + 8 pad
#define STAGE_FLOATS (KC*A_STRIDE + KC*B_STRIDE)   // 1152 + 2176 = 3328
#define SMEM_BYTES   (STAGES*STAGE_FLOATS*4)       // 79872

// ---------------- scratch (device globals: no allocations allowed) ----------
__device__ float  g_xT[Cn*Hn*Wn*Bn];                 // normalized, tf32-rounded, [chw][b]
__device__ __half g_scratch[(size_t)Pn*Bn*COUT];     // GEMM out [p][b][c], fp16
__device__ float  g_inv[Bn];
__device__ float  g_sum[COUT];
__device__ float  g_sq[COUT];

// ---------------- small PTX helpers -----------------------------------------
__device__ __forceinline__ uint32_t f2tf32(float f) {
    uint32_t u;
    asm("cvt.rna.tf32.f32 %0, %1;" : "=r"(u) : "f"(f));
    return u;
}
__device__ __forceinline__ void cp16(uint32_t smem_dst, const void* gmem_src) {
    asm volatile("cp.async.cg.shared.global [%0], [%1], 16;\n"
                 :: "r"(smem_dst), "l"(gmem_src));
}
__device__ __forceinline__ void mma_tf32(float* c, const uint32_t* a, const uint32_t* b) {
    asm volatile(
        "mma.sync.aligned.m16n8k8.row.col.f32.tf32.tf32.f32 "
        "{%0,%1,%2,%3}, {%4,%5,%6,%7}, {%8,%9}, {%0,%1,%2,%3};\n"
        : "+f"(c[0]), "+f"(c[1]), "+f"(c[2]), "+f"(c[3])
        : "r"(a[0]), "r"(a[1]), "r"(a[2]), "r"(a[3]), "r"(b[0]), "r"(b[1]));
}

// ---------------- K0: zero BN stat accumulators ------------------------------
__global__ void k_zero() {
    int tid = threadIdx.x;
    if (tid < COUT) g_sum[tid] = 0.f; else g_sq[tid - COUT] = 0.f;
}

// ---------------- K1: per-batch L2 norm --------------------------------------
__global__ void k_norm(const float* __restrict__ x) {
    int b = blockIdx.x, tid = threadIdx.x;
    const float4* xb = (const float4*)(x + b * (Cn*Hn*Wn));
    float s = 0.f;
    #pragma unroll
    for (int j = 0; j < 36; ++j) {      // 36 * 256 = 9216 float4 = 36864 floats
        float4 v = xb[tid + j * 256];
        s += v.x*v.x + v.y*v.y + v.z*v.z + v.w*v.w;
    }
    __shared__ float red[8];
    #pragma unroll
    for (int o = 16; o; o >>= 1) s += __shfl_xor_sync(~0u, s, o);
    if ((tid & 31) == 0) red[tid >> 5] = s;
    __syncthreads();
    if (tid < 32) {
        float t = (tid < 8) ? red[tid] : 0.f;
        #pragma unroll
        for (int o = 4; o; o >>= 1) t += __shfl_xor_sync(~0u, t, o);
        if (tid == 0) g_inv[b] = 1.f / (sqrtf(t) + 1e-7f);
    }
}

// ---------------- K2: normalize + transpose x -> xT[chw][b] (tf32-rounded) --
__global__ void k_xt(const float* __restrict__ x) {
    __shared__ float tile[64][33];
    int chw0 = blockIdx.x * 32;
    int tx = threadIdx.x & 31, ty = threadIdx.x >> 5;
    #pragma unroll
    for (int i = 0; i < 8; ++i) {
        int bb = ty + i * 8;
        float v = x[bb * (Cn*Hn*Wn) + chw0 + tx] * g_inv[bb];
        tile[bb][tx] = __uint_as_float(f2tf32(v));
    }
    __syncthreads();
    #pragma unroll
    for (int i = 0; i < 8; ++i) {
        int idx = threadIdx.x + i * 256;
        int cl = idx >> 6, bb = idx & 63;
        g_xT[(chw0 + cl) * 64 + bb] = tile[bb][cl];
    }
}

// ---------------- K3: per-position GEMM (tf32 mma.sync, 6-stage pipeline) ---
__device__ __forceinline__ void load_chunk(float* stage, const float* kbase,
                                           int k0, int oh, int ow, int tid) {
    // A: 16 rows (f) x 64 (b): 256 pieces of 16B -> exactly 1 per thread
    {
        int kk = tid >> 4, mseg = tid & 15;
        int f  = k0 + kk;
        int c  = f / 25; int rem = f - c * 25;
        int r  = rem / 5; int s = rem - r * 5;
        const float* src = g_xT + ((c * Hn + oh + r) * Wn + (ow + s)) * 64 + mseg * 4;
        cp16((uint32_t)__cvta_generic_to_shared(&stage[kk * A_STRIDE + mseg * 4]), src);
    }
    // B: 16 rows (f) x 128 (cout): 512 pieces -> 2 per thread
    float* Bbuf = stage + KC * A_STRIDE;
    #pragma unroll
    for (int j = 0; j < 2; ++j) {
        int idx  = tid + j * 256;
        int kk   = idx >> 5, nseg = idx & 31;
        const float* src = kbase + (k0 + kk) * COUT + nseg * 4;
        cp16((uint32_t)__cvta_generic_to_shared(&Bbuf[kk * B_STRIDE + nseg * 4]), src);
    }
}

__global__ void __launch_bounds__(256, 2) k_gemm(const float* __restrict__ kern) {
    extern __shared__ float sm[];
    const int p = blockIdx.x;
    const int oh = p / OWn, ow = p - oh * OWn;
    const int tid = threadIdx.x;
    const int lane = tid & 31, warp = tid >> 5;
    const int g = lane >> 2, tg = lane & 3;
    const int m_off = (warp >> 2) * 32;   // 2 warps over M=64
    const int n_off = (warp & 3) * 32;    // 4 warps over N=128
    const int mhalf = warp >> 2;

    const float* kbase = kern + (size_t)p * (Fn * COUT);

    float acc[2][4][4];
    #pragma unroll
    for (int mt = 0; mt < 2; ++mt)
        #pragma unroll
        for (int nt = 0; nt < 4; ++nt)
            #pragma unroll
            for (int q = 0; q < 4; ++q) acc[mt][nt][q] = 0.f;

    // prologue: prefetch chunks 0..PREF-1 (group index == chunk index)
    #pragma unroll
    for (int c0 = 0; c0 < PREF; ++c0) {
        load_chunk(sm + c0 * STAGE_FLOATS, kbase, c0 * KC, oh, ow, tid);
        asm volatile("cp.async.commit_group;\n");
    }

    for (int ch = 0; ch < NCHUNK; ++ch) {
        int nx = ch + PREF;
        if (nx < NCHUNK)
            load_chunk(sm + (nx % STAGES) * STAGE_FLOATS, kbase, nx * KC, oh, ow, tid);
        asm volatile("cp.async.commit_group;\n");           // dummy in tail: keeps count
        asm volatile("cp.async.wait_group 4;\n");           // group `ch` complete
        __syncthreads();

        const float* stage = sm + (ch % STAGES) * STAGE_FLOATS;
        const uint32_t* As = (const uint32_t*)stage;        // already tf32
        const float*    Bs = stage + KC * A_STRIDE;

        #pragma unroll
        for (int ks = 0; ks < KC; ks += 8) {
            uint32_t a[2][4], b[4][2];
            #pragma unroll
            for (int mt = 0; mt < 2; ++mt) {
                int rm = m_off + mt * 16 + g;
                a[mt][0] = As[(ks + tg    ) * A_STRIDE + rm    ];
                a[mt][1] = As[(ks + tg    ) * A_STRIDE + rm + 8];
                a[mt][2] = As[(ks + tg + 4) * A_STRIDE + rm    ];
                a[mt][3] = As[(ks + tg + 4) * A_STRIDE + rm + 8];
            }
            #pragma unroll
            for (int nt = 0; nt < 4; ++nt) {
                int cn = n_off + nt * 8 + g;
                b[nt][0] = f2tf32(Bs[(ks + tg    ) * B_STRIDE + cn]);
                b[nt][1] = f2tf32(Bs[(ks + tg + 4) * B_STRIDE + cn]);
            }
            #pragma unroll
            for (int mt = 0; mt < 2; ++mt)
                #pragma unroll
                for (int nt = 0; nt < 4; ++nt)
                    mma_tf32(acc[mt][nt], a[mt], b[nt]);
        }
        __syncthreads();
    }

    // epilogue 1: scratch[p][b][c] as fp16 (half2 stores)
    __half* outp = g_scratch + (size_t)p * (Bn * COUT);
    #pragma unroll
    for (int mt = 0; mt < 2; ++mt)
        #pragma unroll
        for (int nt = 0; nt < 4; ++nt) {
            int row = m_off + mt * 16 + g;
            int col = n_off + nt * 8 + 2 * tg;
            *(__half2*)(outp + row * COUT + col)       = __floats2half2_rn(acc[mt][nt][0], acc[mt][nt][1]);
            *(__half2*)(outp + (row + 8) * COUT + col) = __floats2half2_rn(acc[mt][nt][2], acc[mt][nt][3]);
        }

    // epilogue 2: fused BN statistics (per-channel sum / sumsq over M=64 rows)
    float ps[4][2], pq[4][2];
    #pragma unroll
    for (int nt = 0; nt < 4; ++nt)
        #pragma unroll
        for (int j = 0; j < 2; ++j) {
            float v0 = acc[0][nt][j],     v1 = acc[0][nt][j + 2];
            float v2 = acc[1][nt][j],     v3 = acc[1][nt][j + 2];
            ps[nt][j] = v0 + v1 + v2 + v3;
            pq[nt][j] = v0*v0 + v1*v1 + v2*v2 + v3*v3;
        }
    #pragma unroll
    for (int o = 4; o < 32; o <<= 1)
        #pragma unroll
        for (int nt = 0; nt < 4; ++nt)
            #pragma unroll
            for (int j = 0; j < 2; ++j) {
                ps[nt][j] += __shfl_xor_sync(~0u, ps[nt][j], o);
                pq[nt][j] += __shfl_xor_sync(~0u, pq[nt][j], o);
            }
    if (g == 0) {
        #pragma unroll
        for (int nt = 0; nt < 4; ++nt)
            #pragma unroll
            for (int j = 0; j < 2; ++j) {
                int col = n_off + nt * 8 + 2 * tg + j;
                sm[mhalf * COUT + col]            = ps[nt][j];
                sm[2 * COUT + mhalf * COUT + col] = pq[nt][j];
            }
    }
    __syncthreads();
    if (tid < COUT) {
        atomicAdd(&g_sum[tid], sm[tid] + sm[COUT + tid]);
    } else {
        int c = tid - COUT;
        atomicAdd(&g_sq[c], sm[2 * COUT + c] + sm[3 * COUT + c]);
    }
}

// ---------------- K4: BN + ReLU + transpose -> (B, COUT, OH, OW) ------------
__global__ void k_out(const float* __restrict__ gamma, const float* __restrict__ beta,
                      float* __restrict__ out) {
    __shared__ float tile[32][33];
    __shared__ float s_scale[32], s_shift[32];
    const float inv_cnt = 1.f / (float)(Bn * Pn);
    int bx = blockIdx.x, cy = blockIdx.y, b = blockIdx.z;
    int tx = threadIdx.x, ty = threadIdx.y;
    int tid = ty * 32 + tx;
    if (tid < 32) {
        int c = cy * 32 + tid;
        float mean = g_sum[c] * inv_cnt;
        float var  = g_sq[c] * inv_cnt - mean * mean;
        float istd = rsqrtf(var + 1e-5f);
        float sc = gamma[c] * istd;
        s_scale[tid] = sc;
        s_shift[tid] = beta[c] - mean * sc;
    }
    int p0 = bx * 32;
    #pragma unroll
    for (int i = 0; i < 4; ++i) {
        int pl = ty + i * 8;
        int pp = p0 + pl;
        float v = 0.f;
        if (pp < Pn) v = __half2float(g_scratch[(size_t)(pp * Bn + b) * COUT + cy * 32 + tx]);
        tile[pl][tx] = v;
    }
    __syncthreads();
    #pragma unroll
    for (int i = 0; i < 4; ++i) {
        int cl = ty + i * 8;
        int pp = p0 + tx;
        if (pp < Pn) {
            float v = tile[tx][cl];
            v = fmaxf(v * s_scale[cl] + s_shift[cl], 0.f);
            out[((size_t)(b * COUT + cy * 32 + cl)) * Pn + pp] = v;
        }
    }
}

// ---------------- launch -----------------------------------------------------
extern "C" void kernel_launch(void* const* d_in, const int* in_sizes, int n_in,
                              void* d_out, int out_size) {
    const float* x     = (const float*)d_in[0];
    const float* kern  = (const float*)d_in[1];
    const float* gamma = (const float*)d_in[2];
    const float* beta  = (const float*)d_in[3];
    float* out = (float*)d_out;
    (void)in_sizes; (void)n_in; (void)out_size;

    k_zero<<<1, 256>>>();
    k_norm<<<Bn, 256>>>(x);
    k_xt<<<(Cn*Hn*Wn)/32, 256>>>(x);
    cudaFuncSetAttribute(k_gemm, cudaFuncAttributeMaxDynamicSharedMemorySize, SMEM_BYTES);
    k_gemm<<<Pn, 256, SMEM_BYTES>>>(kern);
    dim3 g5((Pn + 31) / 32, COUT / 32, Bn), b5(32, 8);
    k_out<<<g5, b5>>>(gamma, beta, out);
}

// round 7
// speedup vs baseline: 1.1090x; 1.0288x over previous
#include <cuda_runtime.h>
#include <cuda_fp16.h>
#include <cstdint>

#define Bn    64
#define Cn    16
#define Hn    48
#define Wn    48
#define COUT  128
#define OHn   44
#define OWn   44
#define Pn    1936
#define Fn    400
#define KC    16            // K-chunk (400 = 25 * 16)
#define NCHUNK 25
#define STAGES 5
#define PREF   4            // chunk-loads in flight
#define A_STRIDE 72         // 64 + 8 pad
#define B_STRIDE 136        // 128 + 8 pad
#define STAGE_FLOATS (KC*A_STRIDE + KC*B_STRIDE)   // 1152 + 2176 = 3328
#define SSB (STAGE_FLOATS*4)                       // stage bytes = 13312
#define SMEM_BYTES (STAGES*SSB + Fn*4)             // 66560 + 1600 = 68160

// ---------------- scratch (device globals: no allocations allowed) ----------
__device__ float  g_xT[Cn*Hn*Wn*Bn];                 // normalized, tf32-rounded, [chw][b]
__device__ __half g_scratch[(size_t)Pn*Bn*COUT];     // GEMM out [p][b][c], fp16
__device__ float  g_inv[Bn];
__device__ float  g_sum[COUT];
__device__ float  g_sq[COUT];
__device__ int    g_aoff[Fn];                        // f -> xT byte offset (p-independent part)

// ---------------- small PTX helpers -----------------------------------------
__device__ __forceinline__ uint32_t f2tf32(float f) {
    uint32_t u;
    asm("cvt.rna.tf32.f32 %0, %1;" : "=r"(u) : "f"(f));
    return u;
}
__device__ __forceinline__ void cp16(uint32_t smem_dst, const void* gmem_src) {
    asm volatile("cp.async.cg.shared.global [%0], [%1], 16;\n"
                 :: "r"(smem_dst), "l"(gmem_src));
}
__device__ __forceinline__ void mma_tf32(float* c, const uint32_t* a, const uint32_t* b) {
    asm volatile(
        "mma.sync.aligned.m16n8k8.row.col.f32.tf32.tf32.f32 "
        "{%0,%1,%2,%3}, {%4,%5,%6,%7}, {%8,%9}, {%0,%1,%2,%3};\n"
        : "+f"(c[0]), "+f"(c[1]), "+f"(c[2]), "+f"(c[3])
        : "r"(a[0]), "r"(a[1]), "r"(a[2]), "r"(a[3]), "r"(b[0]), "r"(b[1]));
}

// ---------------- K0: zero BN stats + build A-offset table -------------------
__global__ void k_zero() {
    int tid = threadIdx.x;
    if (tid < COUT) g_sum[tid] = 0.f; else g_sq[tid - COUT] = 0.f;
    for (int f = tid; f < Fn; f += 256) {
        int c = f / 25, rem = f % 25, r = rem / 5, s = rem % 5;
        g_aoff[f] = ((c * Hn + r) * Wn + s) * (Bn * 4);   // byte offset
    }
}

// ---------------- K1: per-batch L2 norm --------------------------------------
__global__ void k_norm(const float* __restrict__ x) {
    int b = blockIdx.x, tid = threadIdx.x;
    const float4* xb = (const float4*)(x + b * (Cn*Hn*Wn));
    float s = 0.f;
    #pragma unroll
    for (int j = 0; j < 36; ++j) {
        float4 v = xb[tid + j * 256];
        s += v.x*v.x + v.y*v.y + v.z*v.z + v.w*v.w;
    }
    __shared__ float red[8];
    #pragma unroll
    for (int o = 16; o; o >>= 1) s += __shfl_xor_sync(~0u, s, o);
    if ((tid & 31) == 0) red[tid >> 5] = s;
    __syncthreads();
    if (tid < 32) {
        float t = (tid < 8) ? red[tid] : 0.f;
        #pragma unroll
        for (int o = 4; o; o >>= 1) t += __shfl_xor_sync(~0u, t, o);
        if (tid == 0) g_inv[b] = 1.f / (sqrtf(t) + 1e-7f);
    }
}

// ---------------- K2: normalize + transpose x -> xT[chw][b] (tf32-rounded) --
__global__ void k_xt(const float* __restrict__ x) {
    __shared__ float tile[64][33];
    int chw0 = blockIdx.x * 32;
    int tx = threadIdx.x & 31, ty = threadIdx.x >> 5;
    #pragma unroll
    for (int i = 0; i < 8; ++i) {
        int bb = ty + i * 8;
        float v = x[bb * (Cn*Hn*Wn) + chw0 + tx] * g_inv[bb];
        tile[bb][tx] = __uint_as_float(f2tf32(v));
    }
    __syncthreads();
    #pragma unroll
    for (int i = 0; i < 8; ++i) {
        int idx = threadIdx.x + i * 256;
        int cl = idx >> 6, bb = idx & 63;
        g_xT[(chw0 + cl) * 64 + bb] = tile[bb][cl];
    }
}

// ---------------- K3: per-position GEMM (tf32 mma.sync, 5-stage pipeline) ---
__global__ void __launch_bounds__(256, 3) k_gemm(const float* __restrict__ kern) {
    extern __shared__ float sm[];
    const int p = blockIdx.x;
    const int oh = p / OWn, ow = p - oh * OWn;
    const int tid = threadIdx.x;
    const int lane = tid & 31, warp = tid >> 5;
    const int g = lane >> 2, tg = lane & 3;
    const int m_off = (warp >> 2) * 32;   // 2 warps over M=64
    const int n_off = (warp & 3) * 32;    // 4 warps over N=128
    const int mhalf = warp >> 2;

    // stage table into smem
    int* tab = (int*)(sm + STAGES * STAGE_FLOATS);
    for (int f = tid; f < Fn; f += 256) tab[f] = g_aoff[f];

    const float* kbase = kern + (size_t)p * (Fn * COUT);
    const uint32_t smem_u32 = (uint32_t)__cvta_generic_to_shared(sm);

    // per-thread constant load-path addressing
    const int akk   = tid >> 4, amseg = tid & 15;
    const char* aptr = (const char*)g_xT + (oh * Wn + ow) * (Bn * 4) + amseg * 16;
    const uint32_t adst = smem_u32 + (uint32_t)(akk * A_STRIDE + amseg * 4) * 4;
    const int bkk = tid >> 5, bnseg = tid & 31;
    const char* bptr0 = (const char*)kbase + (uint32_t)(bkk * COUT + bnseg * 4) * 4;
    const char* bptr1 = bptr0 + 8 * COUT * 4;
    const uint32_t bdst0 = smem_u32 + (uint32_t)(KC*A_STRIDE + bkk * B_STRIDE + bnseg * 4) * 4;
    const uint32_t bdst1 = bdst0 + (uint32_t)(8 * B_STRIDE) * 4;

    float acc[2][4][4];
    #pragma unroll
    for (int mt = 0; mt < 2; ++mt)
        #pragma unroll
        for (int nt = 0; nt < 4; ++nt)
            #pragma unroll
            for (int q = 0; q < 4; ++q) acc[mt][nt][q] = 0.f;

    __syncthreads();                       // tab visible to all

    // prologue: chunks 0..PREF-1 into stages 0..PREF-1
    #pragma unroll
    for (int c0 = 0; c0 < PREF; ++c0) {
        uint32_t so = (uint32_t)(c0 * SSB);
        cp16(adst + so, aptr + tab[c0 * KC + akk]);
        cp16(bdst0 + so, bptr0 + c0 * (KC * COUT * 4));
        cp16(bdst1 + so, bptr1 + c0 * (KC * COUT * 4));
        asm volatile("cp.async.commit_group;\n");
    }

    int wstage = PREF, rstage = 0;
    for (int ch = 0; ch < NCHUNK; ++ch) {
        int nx = ch + PREF;
        if (nx < NCHUNK) {
            uint32_t so = (uint32_t)(wstage * SSB);
            cp16(adst + so, aptr + tab[nx * KC + akk]);
            cp16(bdst0 + so, bptr0 + nx * (KC * COUT * 4));
            cp16(bdst1 + so, bptr1 + nx * (KC * COUT * 4));
        }
        asm volatile("cp.async.commit_group;\n");           // dummy in tail keeps count
        asm volatile("cp.async.wait_group 4;\n");           // chunk `ch` complete
        __syncthreads();

        const float* stage = sm + rstage * STAGE_FLOATS;
        const uint32_t* As = (const uint32_t*)stage;        // already tf32
        const float*    Bs = stage + KC * A_STRIDE;

        #pragma unroll
        for (int ks = 0; ks < KC; ks += 8) {
            uint32_t a[2][4], b[4][2];
            #pragma unroll
            for (int mt = 0; mt < 2; ++mt) {
                int rm = m_off + mt * 16 + g;
                a[mt][0] = As[(ks + tg    ) * A_STRIDE + rm    ];
                a[mt][1] = As[(ks + tg    ) * A_STRIDE + rm + 8];
                a[mt][2] = As[(ks + tg + 4) * A_STRIDE + rm    ];
                a[mt][3] = As[(ks + tg + 4) * A_STRIDE + rm + 8];
            }
            #pragma unroll
            for (int nt = 0; nt < 4; ++nt) {
                int cn = n_off + nt * 8 + g;
                b[nt][0] = f2tf32(Bs[(ks + tg    ) * B_STRIDE + cn]);
                b[nt][1] = f2tf32(Bs[(ks + tg + 4) * B_STRIDE + cn]);
            }
            #pragma unroll
            for (int mt = 0; mt < 2; ++mt)
                #pragma unroll
                for (int nt = 0; nt < 4; ++nt)
                    mma_tf32(acc[mt][nt], a[mt], b[nt]);
        }
        __syncthreads();
        if (++wstage == STAGES) wstage = 0;
        if (++rstage == STAGES) rstage = 0;
    }

    // epilogue 1: scratch[p][b][c] as fp16 (half2 stores)
    __half* outp = g_scratch + (size_t)p * (Bn * COUT);
    #pragma unroll
    for (int mt = 0; mt < 2; ++mt)
        #pragma unroll
        for (int nt = 0; nt < 4; ++nt) {
            int row = m_off + mt * 16 + g;
            int col = n_off + nt * 8 + 2 * tg;
            *(__half2*)(outp + row * COUT + col)       = __floats2half2_rn(acc[mt][nt][0], acc[mt][nt][1]);
            *(__half2*)(outp + (row + 8) * COUT + col) = __floats2half2_rn(acc[mt][nt][2], acc[mt][nt][3]);
        }

    // epilogue 2: fused BN statistics (per-channel sum / sumsq over M=64 rows)
    float ps[4][2], pq[4][2];
    #pragma unroll
    for (int nt = 0; nt < 4; ++nt)
        #pragma unroll
        for (int j = 0; j < 2; ++j) {
            float v0 = acc[0][nt][j],     v1 = acc[0][nt][j + 2];
            float v2 = acc[1][nt][j],     v3 = acc[1][nt][j + 2];
            ps[nt][j] = v0 + v1 + v2 + v3;
            pq[nt][j] = v0*v0 + v1*v1 + v2*v2 + v3*v3;
        }
    #pragma unroll
    for (int o = 4; o < 32; o <<= 1)
        #pragma unroll
        for (int nt = 0; nt < 4; ++nt)
            #pragma unroll
            for (int j = 0; j < 2; ++j) {
                ps[nt][j] += __shfl_xor_sync(~0u, ps[nt][j], o);
                pq[nt][j] += __shfl_xor_sync(~0u, pq[nt][j], o);
            }
    if (g == 0) {
        #pragma unroll
        for (int nt = 0; nt < 4; ++nt)
            #pragma unroll
            for (int j = 0; j < 2; ++j) {
                int col = n_off + nt * 8 + 2 * tg + j;
                sm[mhalf * COUT + col]            = ps[nt][j];
                sm[2 * COUT + mhalf * COUT + col] = pq[nt][j];
            }
    }
    __syncthreads();
    if (tid < COUT) {
        atomicAdd(&g_sum[tid], sm[tid] + sm[COUT + tid]);
    } else {
        int c = tid - COUT;
        atomicAdd(&g_sq[c], sm[2 * COUT + c] + sm[3 * COUT + c]);
    }
}

// ---------------- K4: BN + ReLU + transpose -> (B, COUT, OH, OW) ------------
__global__ void k_out(const float* __restrict__ gamma, const float* __restrict__ beta,
                      float* __restrict__ out) {
    __shared__ float tile[32][33];
    __shared__ float s_scale[32], s_shift[32];
    const float inv_cnt = 1.f / (float)(Bn * Pn);
    int bx = blockIdx.x, cy = blockIdx.y, b = blockIdx.z;
    int tx = threadIdx.x, ty = threadIdx.y;
    int tid = ty * 32 + tx;
    if (tid < 32) {
        int c = cy * 32 + tid;
        float mean = g_sum[c] * inv_cnt;
        float var  = g_sq[c] * inv_cnt - mean * mean;
        float istd = rsqrtf(var + 1e-5f);
        float sc = gamma[c] * istd;
        s_scale[tid] = sc;
        s_shift[tid] = beta[c] - mean * sc;
    }
    int p0 = bx * 32;
    #pragma unroll
    for (int i = 0; i < 4; ++i) {
        int pl = ty + i * 8;
        int pp = p0 + pl;
        float v = 0.f;
        if (pp < Pn) v = __half2float(g_scratch[(size_t)(pp * Bn + b) * COUT + cy * 32 + tx]);
        tile[pl][tx] = v;
    }
    __syncthreads();
    #pragma unroll
    for (int i = 0; i < 4; ++i) {
        int cl = ty + i * 8;
        int pp = p0 + tx;
        if (pp < Pn) {
            float v = tile[tx][cl];
            v = fmaxf(v * s_scale[cl] + s_shift[cl], 0.f);
            out[((size_t)(b * COUT + cy * 32 + cl)) * Pn + pp] = v;
        }
    }
}

// ---------------- launch -----------------------------------------------------
extern "C" void kernel_launch(void* const* d_in, const int* in_sizes, int n_in,
                              void* d_out, int out_size) {
    const float* x     = (const float*)d_in[0];
    const float* kern  = (const float*)d_in[1];
    const float* gamma = (const float*)d_in[2];
    const float* beta  = (const float*)d_in[3];
    float* out = (float*)d_out;
    (void)in_sizes; (void)n_in; (void)out_size;

    k_zero<<<1, 256>>>();
    k_norm<<<Bn, 256>>>(x);
    k_xt<<<(Cn*Hn*Wn)/32, 256>>>(x);
    cudaFuncSetAttribute(k_gemm, cudaFuncAttributeMaxDynamicSharedMemorySize, SMEM_BYTES);
    k_gemm<<<Pn, 256, SMEM_BYTES>>>(kern);
    dim3 g5((Pn + 31) / 32, COUT / 32, Bn), b5(32, 8);
    k_out<<<g5, b5>>>(gamma, beta, out);
}

// round 8
// speedup vs baseline: 1.1214x; 1.0112x over previous
#include <cuda_runtime.h>
#include <cuda_fp16.h>
#include <cstdint>

#define Bn    64
#define Cn    16
#define Hn    48
#define Wn    48
#define COUT  128
#define OHn   44
#define OWn   44
#define Pn    1936
#define Fn    400
#define KC    16            // K-chunk (400 = 25 * 16)
#define NCHUNK 25
#define STAGES 5
#define PREF   4            // chunk-loads in flight
#define A_STRIDE 72         // 64 + 8 pad
#define B_STRIDE 136        // 128 + 8 pad
#define STAGE_FLOATS (KC*A_STRIDE + KC*B_STRIDE)   // 1152 + 2176 = 3328
#define SSB (STAGE_FLOATS*4)                       // stage bytes = 13312
#define SMEM_BYTES (STAGES*SSB + Fn*4)             // 66560 + 1600 = 68160

// ---------------- scratch (device globals: no allocations allowed) ----------
__device__ float  g_xT[Cn*Hn*Wn*Bn];                 // normalized, tf32-rounded, [chw][b]
__device__ __half g_scratch[(size_t)Pn*Bn*COUT];     // GEMM out [p][b][c], fp16
__device__ float  g_inv[Bn];
__device__ float  g_sum[COUT];
__device__ float  g_sq[COUT];
__device__ int    g_aoff[Fn];                        // f -> xT byte offset (p-independent part)

// ---------------- small PTX helpers -----------------------------------------
__device__ __forceinline__ uint32_t f2tf32(float f) {
    uint32_t u;
    asm("cvt.rna.tf32.f32 %0, %1;" : "=r"(u) : "f"(f));
    return u;
}
__device__ __forceinline__ void cp16(uint32_t smem_dst, const void* gmem_src) {
    asm volatile("cp.async.cg.shared.global [%0], [%1], 16;\n"
                 :: "r"(smem_dst), "l"(gmem_src));
}
__device__ __forceinline__ void mma_tf32(float* c, const uint32_t* a, const uint32_t* b) {
    asm volatile(
        "mma.sync.aligned.m16n8k8.row.col.f32.tf32.tf32.f32 "
        "{%0,%1,%2,%3}, {%4,%5,%6,%7}, {%8,%9}, {%0,%1,%2,%3};\n"
        : "+f"(c[0]), "+f"(c[1]), "+f"(c[2]), "+f"(c[3])
        : "r"(a[0]), "r"(a[1]), "r"(a[2]), "r"(a[3]), "r"(b[0]), "r"(b[1]));
}

// ---------------- K0: zero BN stats + build A-offset table -------------------
__global__ void k_zero() {
    int tid = threadIdx.x;
    if (tid < COUT) g_sum[tid] = 0.f; else g_sq[tid - COUT] = 0.f;
    for (int f = tid; f < Fn; f += 256) {
        int c = f / 25, rem = f % 25, r = rem / 5, s = rem % 5;
        g_aoff[f] = ((c * Hn + r) * Wn + s) * (Bn * 4);   // byte offset
    }
}

// ---------------- K1: per-batch L2 norm --------------------------------------
__global__ void k_norm(const float* __restrict__ x) {
    int b = blockIdx.x, tid = threadIdx.x;
    const float4* xb = (const float4*)(x + b * (Cn*Hn*Wn));
    float s = 0.f;
    #pragma unroll
    for (int j = 0; j < 36; ++j) {
        float4 v = xb[tid + j * 256];
        s += v.x*v.x + v.y*v.y + v.z*v.z + v.w*v.w;
    }
    __shared__ float red[8];
    #pragma unroll
    for (int o = 16; o; o >>= 1) s += __shfl_xor_sync(~0u, s, o);
    if ((tid & 31) == 0) red[tid >> 5] = s;
    __syncthreads();
    if (tid < 32) {
        float t = (tid < 8) ? red[tid] : 0.f;
        #pragma unroll
        for (int o = 4; o; o >>= 1) t += __shfl_xor_sync(~0u, t, o);
        if (tid == 0) g_inv[b] = 1.f / (sqrtf(t) + 1e-7f);
    }
}

// ---------------- K2: normalize + transpose x -> xT[chw][b] (tf32-rounded) --
__global__ void k_xt(const float* __restrict__ x) {
    __shared__ float tile[64][33];
    int chw0 = blockIdx.x * 32;
    int tx = threadIdx.x & 31, ty = threadIdx.x >> 5;
    #pragma unroll
    for (int i = 0; i < 8; ++i) {
        int bb = ty + i * 8;
        float v = x[bb * (Cn*Hn*Wn) + chw0 + tx] * g_inv[bb];
        tile[bb][tx] = __uint_as_float(f2tf32(v));
    }
    __syncthreads();
    #pragma unroll
    for (int i = 0; i < 8; ++i) {
        int idx = threadIdx.x + i * 256;
        int cl = idx >> 6, bb = idx & 63;
        g_xT[(chw0 + cl) * 64 + bb] = tile[bb][cl];
    }
}

// ---------------- K3: per-position GEMM (tf32 mma.sync, 5-stage pipeline) ---
__global__ void __launch_bounds__(256, 3) k_gemm(const float* __restrict__ kern) {
    extern __shared__ float sm[];
    const int p = blockIdx.x;
    const int oh = p / OWn, ow = p - oh * OWn;
    const int tid = threadIdx.x;
    const int lane = tid & 31, warp = tid >> 5;
    const int g = lane >> 2, tg = lane & 3;
    const int m_off = (warp >> 2) * 32;   // 2 warps over M=64
    const int n_off = (warp & 3) * 32;    // 4 warps over N=128
    const int mhalf = warp >> 2;

    // stage table into smem
    int* tab = (int*)(sm + STAGES * STAGE_FLOATS);
    for (int f = tid; f < Fn; f += 256) tab[f] = g_aoff[f];

    const float* kbase = kern + (size_t)p * (Fn * COUT);
    const uint32_t smem_u32 = (uint32_t)__cvta_generic_to_shared(sm);

    // per-thread constant load-path addressing
    const int akk   = tid >> 4, amseg = tid & 15;
    const char* aptr = (const char*)g_xT + (oh * Wn + ow) * (Bn * 4) + amseg * 16;
    const uint32_t adst = smem_u32 + (uint32_t)(akk * A_STRIDE + amseg * 4) * 4;
    const int bkk = tid >> 5, bnseg = tid & 31;
    const char* bptr0 = (const char*)kbase + (uint32_t)(bkk * COUT + bnseg * 4) * 4;
    const char* bptr1 = bptr0 + 8 * COUT * 4;
    const uint32_t bdst0 = smem_u32 + (uint32_t)(KC*A_STRIDE + bkk * B_STRIDE + bnseg * 4) * 4;
    const uint32_t bdst1 = bdst0 + (uint32_t)(8 * B_STRIDE) * 4;

    float acc[2][4][4];
    #pragma unroll
    for (int mt = 0; mt < 2; ++mt)
        #pragma unroll
        for (int nt = 0; nt < 4; ++nt)
            #pragma unroll
            for (int q = 0; q < 4; ++q) acc[mt][nt][q] = 0.f;

    __syncthreads();                       // tab visible to all

    // prologue: chunks 0..PREF-1 into stages 0..PREF-1
    #pragma unroll
    for (int c0 = 0; c0 < PREF; ++c0) {
        uint32_t so = (uint32_t)(c0 * SSB);
        cp16(adst + so, aptr + tab[c0 * KC + akk]);
        cp16(bdst0 + so, bptr0 + c0 * (KC * COUT * 4));
        cp16(bdst1 + so, bptr1 + c0 * (KC * COUT * 4));
        asm volatile("cp.async.commit_group;\n");
    }

    int wstage = PREF, rstage = 0;
    for (int ch = 0; ch < NCHUNK; ++ch) {
        int nx = ch + PREF;
        if (nx < NCHUNK) {
            uint32_t so = (uint32_t)(wstage * SSB);
            cp16(adst + so, aptr + tab[nx * KC + akk]);
            cp16(bdst0 + so, bptr0 + nx * (KC * COUT * 4));
            cp16(bdst1 + so, bptr1 + nx * (KC * COUT * 4));
        }
        asm volatile("cp.async.commit_group;\n");           // dummy in tail keeps count
        asm volatile("cp.async.wait_group 4;\n");           // chunk `ch` complete
        __syncthreads();

        const float* stage = sm + rstage * STAGE_FLOATS;
        const uint32_t* As = (const uint32_t*)stage;        // already tf32
        const float*    Bs = stage + KC * A_STRIDE;

        #pragma unroll
        for (int ks = 0; ks < KC; ks += 8) {
            uint32_t a[2][4], b[4][2];
            #pragma unroll
            for (int mt = 0; mt < 2; ++mt) {
                int rm = m_off + mt * 16 + g;
                a[mt][0] = As[(ks + tg    ) * A_STRIDE + rm    ];
                a[mt][1] = As[(ks + tg    ) * A_STRIDE + rm + 8];
                a[mt][2] = As[(ks + tg + 4) * A_STRIDE + rm    ];
                a[mt][3] = As[(ks + tg + 4) * A_STRIDE + rm + 8];
            }
            #pragma unroll
            for (int nt = 0; nt < 4; ++nt) {
                int cn = n_off + nt * 8 + g;
                b[nt][0] = f2tf32(Bs[(ks + tg    ) * B_STRIDE + cn]);
                b[nt][1] = f2tf32(Bs[(ks + tg + 4) * B_STRIDE + cn]);
            }
            #pragma unroll
            for (int mt = 0; mt < 2; ++mt)
                #pragma unroll
                for (int nt = 0; nt < 4; ++nt)
                    mma_tf32(acc[mt][nt], a[mt], b[nt]);
        }
        __syncthreads();
        if (++wstage == STAGES) wstage = 0;
        if (++rstage == STAGES) rstage = 0;
    }

    // epilogue 1: scratch[p][b][c] as fp16 (half2 stores)
    __half* outp = g_scratch + (size_t)p * (Bn * COUT);
    #pragma unroll
    for (int mt = 0; mt < 2; ++mt)
        #pragma unroll
        for (int nt = 0; nt < 4; ++nt) {
            int row = m_off + mt * 16 + g;
            int col = n_off + nt * 8 + 2 * tg;
            *(__half2*)(outp + row * COUT + col)       = __floats2half2_rn(acc[mt][nt][0], acc[mt][nt][1]);
            *(__half2*)(outp + (row + 8) * COUT + col) = __floats2half2_rn(acc[mt][nt][2], acc[mt][nt][3]);
        }

    // epilogue 2: fused BN statistics (per-channel sum / sumsq over M=64 rows)
    float ps[4][2], pq[4][2];
    #pragma unroll
    for (int nt = 0; nt < 4; ++nt)
        #pragma unroll
        for (int j = 0; j < 2; ++j) {
            float v0 = acc[0][nt][j],     v1 = acc[0][nt][j + 2];
            float v2 = acc[1][nt][j],     v3 = acc[1][nt][j + 2];
            ps[nt][j] = v0 + v1 + v2 + v3;
            pq[nt][j] = v0*v0 + v1*v1 + v2*v2 + v3*v3;
        }
    #pragma unroll
    for (int o = 4; o < 32; o <<= 1)
        #pragma unroll
        for (int nt = 0; nt < 4; ++nt)
            #pragma unroll
            for (int j = 0; j < 2; ++j) {
                ps[nt][j] += __shfl_xor_sync(~0u, ps[nt][j], o);
                pq[nt][j] += __shfl_xor_sync(~0u, pq[nt][j], o);
            }
    if (g == 0) {
        #pragma unroll
        for (int nt = 0; nt < 4; ++nt)
            #pragma unroll
            for (int j = 0; j < 2; ++j) {
                int col = n_off + nt * 8 + 2 * tg + j;
                sm[mhalf * COUT + col]            = ps[nt][j];
                sm[2 * COUT + mhalf * COUT + col] = pq[nt][j];
            }
    }
    __syncthreads();
    if (tid < COUT) {
        atomicAdd(&g_sum[tid], sm[tid] + sm[COUT + tid]);
    } else {
        int c = tid - COUT;
        atomicAdd(&g_sq[c], sm[2 * COUT + c] + sm[3 * COUT + c]);
    }
}

// ---------------- K4: BN + ReLU + transpose -> (B, COUT, OH, OW) ------------
__global__ void k_out(const float* __restrict__ gamma, const float* __restrict__ beta,
                      float* __restrict__ out) {
    __shared__ float tile[32][33];
    __shared__ float s_scale[32], s_shift[32];
    const float inv_cnt = 1.f / (float)(Bn * Pn);
    int bx = blockIdx.x, cy = blockIdx.y, b = blockIdx.z;
    int tx = threadIdx.x, ty = threadIdx.y;
    int tid = ty * 32 + tx;
    if (tid < 32) {
        int c = cy * 32 + tid;
        float mean = g_sum[c] * inv_cnt;
        float var  = g_sq[c] * inv_cnt - mean * mean;
        float istd = rsqrtf(var + 1e-5f);
        float sc = gamma[c] * istd;
        s_scale[tid] = sc;
        s_shift[tid] = beta[c] - mean * sc;
    }
    int p0 = bx * 32;
    #pragma unroll
    for (int i = 0; i < 4; ++i) {
        int pl = ty + i * 8;
        int pp = p0 + pl;
        float v = 0.f;
        if (pp < Pn) v = __half2float(g_scratch[(size_t)(pp * Bn + b) * COUT + cy * 32 + tx]);
        tile[pl][tx] = v;
    }
    __syncthreads();
    #pragma unroll
    for (int i = 0; i < 4; ++i) {
        int cl = ty + i * 8;
        int pp = p0 + tx;
        if (pp < Pn) {
            float v = tile[tx][cl];
            v = fmaxf(v * s_scale[cl] + s_shift[cl], 0.f);
            out[((size_t)(b * COUT + cy * 32 + cl)) * Pn + pp] = v;
        }
    }
}

// ---------------- launch -----------------------------------------------------
extern "C" void kernel_launch(void* const* d_in, const int* in_sizes, int n_in,
                              void* d_out, int out_size) {
    const float* x     = (const float*)d_in[0];
    const float* kern  = (const float*)d_in[1];
    const float* gamma = (const float*)d_in[2];
    const float* beta  = (const float*)d_in[3];
    float* out = (float*)d_out;
    (void)in_sizes; (void)n_in; (void)out_size;

    k_zero<<<1, 256>>>();
    k_norm<<<Bn, 256>>>(x);
    k_xt<<<(Cn*Hn*Wn)/32, 256>>>(x);
    cudaFuncSetAttribute(k_gemm, cudaFuncAttributeMaxDynamicSharedMemorySize, SMEM_BYTES);
    k_gemm<<<Pn, 256, SMEM_BYTES>>>(kern);
    dim3 g5((Pn + 31) / 32, COUT / 32, Bn), b5(32, 8);
    k_out<<<g5, b5>>>(gamma, beta, out);
}

// round 9
// speedup vs baseline: 1.1216x; 1.0002x over previous
#include <cuda_runtime.h>
#include <cuda_fp16.h>
#include <cstdint>

#define Bn    64
#define Cn    16
#define Hn    48
#define Wn    48
#define COUT  128
#define OHn   44
#define OWn   44
#define Pn    1936
#define Fn    400
#define KC    16            // K-chunk (400 = 25 * 16)
#define NCHUNK 25
#define STAGES 5
#define PREF   4            // chunk-loads in flight
#define A_STRIDE 72         // 64 + 8 pad
#define B_STRIDE 136        // 128 + 8 pad
#define STAGE_FLOATS (KC*A_STRIDE + KC*B_STRIDE)   // 1152 + 2176 = 3328
#define SSB (STAGE_FLOATS*4)                       // stage bytes = 13312
#define SMEM_BYTES (STAGES*SSB + Fn*4)             // 66560 + 1600 = 68160

// ---------------- scratch (device globals: no allocations allowed) ----------
__device__ float  g_xT[Cn*Hn*Wn*Bn];                 // normalized, tf32-rounded, [chw][b]
__device__ __half g_scratch[(size_t)Pn*Bn*COUT];     // GEMM out [p][b][c], fp16
__device__ float  g_inv[Bn];
__device__ float  g_sum[COUT];
__device__ float  g_sq[COUT];
__device__ int    g_aoff[Fn];                        // f -> xT byte offset (p-independent part)

// ---------------- small PTX helpers -----------------------------------------
__device__ __forceinline__ uint32_t f2tf32(float f) {
    uint32_t u;
    asm("cvt.rna.tf32.f32 %0, %1;" : "=r"(u) : "f"(f));
    return u;
}
__device__ __forceinline__ void cp16(uint32_t smem_dst, const void* gmem_src) {
    asm volatile("cp.async.cg.shared.global [%0], [%1], 16;\n"
                 :: "r"(smem_dst), "l"(gmem_src));
}
__device__ __forceinline__ void mma_tf32(float* c, const uint32_t* a, const uint32_t* b) {
    asm volatile(
        "mma.sync.aligned.m16n8k8.row.col.f32.tf32.tf32.f32 "
        "{%0,%1,%2,%3}, {%4,%5,%6,%7}, {%8,%9}, {%0,%1,%2,%3};\n"
        : "+f"(c[0]), "+f"(c[1]), "+f"(c[2]), "+f"(c[3])
        : "r"(a[0]), "r"(a[1]), "r"(a[2]), "r"(a[3]), "r"(b[0]), "r"(b[1]));
}

// ---------------- K0: zero BN stats + build A-offset table -------------------
__global__ void k_zero() {
    int tid = threadIdx.x;
    if (tid < COUT) g_sum[tid] = 0.f; else g_sq[tid - COUT] = 0.f;
    for (int f = tid; f < Fn; f += 256) {
        int c = f / 25, rem = f % 25, r = rem / 5, s = rem % 5;
        g_aoff[f] = ((c * Hn + r) * Wn + s) * (Bn * 4);   // byte offset
    }
}

// ---------------- K1: per-batch L2 norm --------------------------------------
__global__ void k_norm(const float* __restrict__ x) {
    int b = blockIdx.x, tid = threadIdx.x;
    const float4* xb = (const float4*)(x + b * (Cn*Hn*Wn));
    float s = 0.f;
    #pragma unroll
    for (int j = 0; j < 36; ++j) {
        float4 v = xb[tid + j * 256];
        s += v.x*v.x + v.y*v.y + v.z*v.z + v.w*v.w;
    }
    __shared__ float red[8];
    #pragma unroll
    for (int o = 16; o; o >>= 1) s += __shfl_xor_sync(~0u, s, o);
    if ((tid & 31) == 0) red[tid >> 5] = s;
    __syncthreads();
    if (tid < 32) {
        float t = (tid < 8) ? red[tid] : 0.f;
        #pragma unroll
        for (int o = 4; o; o >>= 1) t += __shfl_xor_sync(~0u, t, o);
        if (tid == 0) g_inv[b] = 1.f / (sqrtf(t) + 1e-7f);
    }
}

// ---------------- K2: normalize + transpose x -> xT[chw][b] (tf32-rounded) --
__global__ void k_xt(const float* __restrict__ x) {
    __shared__ float tile[64][33];
    int chw0 = blockIdx.x * 32;
    int tx = threadIdx.x & 31, ty = threadIdx.x >> 5;
    #pragma unroll
    for (int i = 0; i < 8; ++i) {
        int bb = ty + i * 8;
        float v = x[bb * (Cn*Hn*Wn) + chw0 + tx] * g_inv[bb];
        tile[bb][tx] = __uint_as_float(f2tf32(v));
    }
    __syncthreads();
    #pragma unroll
    for (int i = 0; i < 8; ++i) {
        int idx = threadIdx.x + i * 256;
        int cl = idx >> 6, bb = idx & 63;
        g_xT[(chw0 + cl) * 64 + bb] = tile[bb][cl];
    }
}

// ---------------- K3: per-position GEMM (tf32 mma.sync, 5-stage pipeline) ---
__global__ void __launch_bounds__(256, 3) k_gemm(const float* __restrict__ kern) {
    extern __shared__ float sm[];
    const int p = blockIdx.x;
    const int oh = p / OWn, ow = p - oh * OWn;
    const int tid = threadIdx.x;
    const int lane = tid & 31, warp = tid >> 5;
    const int g = lane >> 2, tg = lane & 3;
    const int m_off = (warp >> 2) * 32;   // 2 warps over M=64
    const int n_off = (warp & 3) * 32;    // 4 warps over N=128
    const int mhalf = warp >> 2;

    // stage table into smem
    int* tab = (int*)(sm + STAGES * STAGE_FLOATS);
    for (int f = tid; f < Fn; f += 256) tab[f] = g_aoff[f];

    const float* kbase = kern + (size_t)p * (Fn * COUT);
    const uint32_t smem_u32 = (uint32_t)__cvta_generic_to_shared(sm);

    // per-thread constant load-path addressing
    const int akk   = tid >> 4, amseg = tid & 15;
    const char* aptr = (const char*)g_xT + (oh * Wn + ow) * (Bn * 4) + amseg * 16;
    const uint32_t adst = smem_u32 + (uint32_t)(akk * A_STRIDE + amseg * 4) * 4;
    const int bkk = tid >> 5, bnseg = tid & 31;
    const char* bptr0 = (const char*)kbase + (uint32_t)(bkk * COUT + bnseg * 4) * 4;
    const char* bptr1 = bptr0 + 8 * COUT * 4;
    const uint32_t bdst0 = smem_u32 + (uint32_t)(KC*A_STRIDE + bkk * B_STRIDE + bnseg * 4) * 4;
    const uint32_t bdst1 = bdst0 + (uint32_t)(8 * B_STRIDE) * 4;

    float acc[2][4][4];
    #pragma unroll
    for (int mt = 0; mt < 2; ++mt)
        #pragma unroll
        for (int nt = 0; nt < 4; ++nt)
            #pragma unroll
            for (int q = 0; q < 4; ++q) acc[mt][nt][q] = 0.f;

    __syncthreads();                       // tab visible to all

    // prologue: chunks 0..PREF-1 into stages 0..PREF-1
    #pragma unroll
    for (int c0 = 0; c0 < PREF; ++c0) {
        uint32_t so = (uint32_t)(c0 * SSB);
        cp16(adst + so, aptr + tab[c0 * KC + akk]);
        cp16(bdst0 + so, bptr0 + c0 * (KC * COUT * 4));
        cp16(bdst1 + so, bptr1 + c0 * (KC * COUT * 4));
        asm volatile("cp.async.commit_group;\n");
    }

    int wstage = PREF, rstage = 0;
    for (int ch = 0; ch < NCHUNK; ++ch) {
        int nx = ch + PREF;
        if (nx < NCHUNK) {
            uint32_t so = (uint32_t)(wstage * SSB);
            cp16(adst + so, aptr + tab[nx * KC + akk]);
            cp16(bdst0 + so, bptr0 + nx * (KC * COUT * 4));
            cp16(bdst1 + so, bptr1 + nx * (KC * COUT * 4));
        }
        asm volatile("cp.async.commit_group;\n");           // dummy in tail keeps count
        asm volatile("cp.async.wait_group 4;\n");           // chunk `ch` complete
        __syncthreads();

        const float* stage = sm + rstage * STAGE_FLOATS;
        const uint32_t* As = (const uint32_t*)stage;        // already tf32
        const float*    Bs = stage + KC * A_STRIDE;

        #pragma unroll
        for (int ks = 0; ks < KC; ks += 8) {
            uint32_t a[2][4], b[4][2];
            #pragma unroll
            for (int mt = 0; mt < 2; ++mt) {
                int rm = m_off + mt * 16 + g;
                a[mt][0] = As[(ks + tg    ) * A_STRIDE + rm    ];
                a[mt][1] = As[(ks + tg    ) * A_STRIDE + rm + 8];
                a[mt][2] = As[(ks + tg + 4) * A_STRIDE + rm    ];
                a[mt][3] = As[(ks + tg + 4) * A_STRIDE + rm + 8];
            }
            #pragma unroll
            for (int nt = 0; nt < 4; ++nt) {
                int cn = n_off + nt * 8 + g;
                b[nt][0] = f2tf32(Bs[(ks + tg    ) * B_STRIDE + cn]);
                b[nt][1] = f2tf32(Bs[(ks + tg + 4) * B_STRIDE + cn]);
            }
            #pragma unroll
            for (int mt = 0; mt < 2; ++mt)
                #pragma unroll
                for (int nt = 0; nt < 4; ++nt)
                    mma_tf32(acc[mt][nt], a[mt], b[nt]);
        }
        __syncthreads();
        if (++wstage == STAGES) wstage = 0;
        if (++rstage == STAGES) rstage = 0;
    }

    // epilogue 1: scratch[p][b][c] as fp16 (half2 stores)
    __half* outp = g_scratch + (size_t)p * (Bn * COUT);
    #pragma unroll
    for (int mt = 0; mt < 2; ++mt)
        #pragma unroll
        for (int nt = 0; nt < 4; ++nt) {
            int row = m_off + mt * 16 + g;
            int col = n_off + nt * 8 + 2 * tg;
            *(__half2*)(outp + row * COUT + col)       = __floats2half2_rn(acc[mt][nt][0], acc[mt][nt][1]);
            *(__half2*)(outp + (row + 8) * COUT + col) = __floats2half2_rn(acc[mt][nt][2], acc[mt][nt][3]);
        }

    // epilogue 2: fused BN statistics (per-channel sum / sumsq over M=64 rows)
    float ps[4][2], pq[4][2];
    #pragma unroll
    for (int nt = 0; nt < 4; ++nt)
        #pragma unroll
        for (int j = 0; j < 2; ++j) {
            float v0 = acc[0][nt][j],     v1 = acc[0][nt][j + 2];
            float v2 = acc[1][nt][j],     v3 = acc[1][nt][j + 2];
            ps[nt][j] = v0 + v1 + v2 + v3;
            pq[nt][j] = v0*v0 + v1*v1 + v2*v2 + v3*v3;
        }
    #pragma unroll
    for (int o = 4; o < 32; o <<= 1)
        #pragma unroll
        for (int nt = 0; nt < 4; ++nt)
            #pragma unroll
            for (int j = 0; j < 2; ++j) {
                ps[nt][j] += __shfl_xor_sync(~0u, ps[nt][j], o);
                pq[nt][j] += __shfl_xor_sync(~0u, pq[nt][j], o);
            }
    if (g == 0) {
        #pragma unroll
        for (int nt = 0; nt < 4; ++nt)
            #pragma unroll
            for (int j = 0; j < 2; ++j) {
                int col = n_off + nt * 8 + 2 * tg + j;
                sm[mhalf * COUT + col]            = ps[nt][j];
                sm[2 * COUT + mhalf * COUT + col] = pq[nt][j];
            }
    }
    __syncthreads();
    if (tid < COUT) {
        atomicAdd(&g_sum[tid], sm[tid] + sm[COUT + tid]);
    } else {
        int c = tid - COUT;
        atomicAdd(&g_sq[c], sm[2 * COUT + c] + sm[3 * COUT + c]);
    }
}

// ---------------- K4: BN + ReLU + transpose -> (B, COUT, OH, OW) ------------
__global__ void k_out(const float* __restrict__ gamma, const float* __restrict__ beta,
                      float* __restrict__ out) {
    __shared__ float tile[32][33];
    __shared__ float s_scale[32], s_shift[32];
    const float inv_cnt = 1.f / (float)(Bn * Pn);
    int bx = blockIdx.x, cy = blockIdx.y, b = blockIdx.z;
    int tx = threadIdx.x, ty = threadIdx.y;
    int tid = ty * 32 + tx;
    if (tid < 32) {
        int c = cy * 32 + tid;
        float mean = g_sum[c] * inv_cnt;
        float var  = g_sq[c] * inv_cnt - mean * mean;
        float istd = rsqrtf(var + 1e-5f);
        float sc = gamma[c] * istd;
        s_scale[tid] = sc;
        s_shift[tid] = beta[c] - mean * sc;
    }
    int p0 = bx * 32;
    #pragma unroll
    for (int i = 0; i < 4; ++i) {
        int pl = ty + i * 8;
        int pp = p0 + pl;
        float v = 0.f;
        if (pp < Pn) v = __half2float(g_scratch[(size_t)(pp * Bn + b) * COUT + cy * 32 + tx]);
        tile[pl][tx] = v;
    }
    __syncthreads();
    #pragma unroll
    for (int i = 0; i < 4; ++i) {
        int cl = ty + i * 8;
        int pp = p0 + tx;
        if (pp < Pn) {
            float v = tile[tx][cl];
            v = fmaxf(v * s_scale[cl] + s_shift[cl], 0.f);
            out[((size_t)(b * COUT + cy * 32 + cl)) * Pn + pp] = v;
        }
    }
}

// ---------------- launch -----------------------------------------------------
extern "C" void kernel_launch(void* const* d_in, const int* in_sizes, int n_in,
                              void* d_out, int out_size) {
    const float* x     = (const float*)d_in[0];
    const float* kern  = (const float*)d_in[1];
    const float* gamma = (const float*)d_in[2];
    const float* beta  = (const float*)d_in[3];
    float* out = (float*)d_out;
    (void)in_sizes; (void)n_in; (void)out_size;

    k_zero<<<1, 256>>>();
    k_norm<<<Bn, 256>>>(x);
    k_xt<<<(Cn*Hn*Wn)/32, 256>>>(x);
    cudaFuncSetAttribute(k_gemm, cudaFuncAttributeMaxDynamicSharedMemorySize, SMEM_BYTES);
    k_gemm<<<Pn, 256, SMEM_BYTES>>>(kern);
    dim3 g5((Pn + 31) / 32, COUT / 32, Bn), b5(32, 8);
    k_out<<<g5, b5>>>(gamma, beta, out);
}